// round 7
// baseline (speedup 1.0000x reference)
#include <cuda_runtime.h>
#include <cuda_fp16.h>
#include <cstdint>
#include <math.h>

// Problem sizes (fixed)
#define NE   32
#define HD   2048
#define ID   1536
#define NTOK 1024
#define TOPK 8
#define NP   (NTOK*TOPK)
#define BM   256
#define MAXMT 64

// ---------------- device scratch ----------------
__device__ int    g_perm[NP];
__device__ float  g_pw[NP];
__device__ int    g_off[NE+1];
__device__ int    g_mt_e[MAXMT];
__device__ int    g_mt_r[MAXMT];
__device__ int    g_nmt;
__device__ __half g_xh[(size_t)NTOK*HD];  // 4 MB fp16 hidden states
__device__ __half g_act[(size_t)NP*ID];   // 24 MB fp16 activations

// ---------------- helpers ----------------
__device__ __forceinline__ uint32_t smem_u32(const void* p){
  uint32_t a;
  asm("{ .reg .u64 t; cvta.to.shared.u64 t, %1; cvt.u32.u64 %0, t; }" : "=r"(a) : "l"(p));
  return a;
}
__device__ __forceinline__ uint32_t f22h(float lo, float hi){
  uint32_t r; asm("cvt.rn.f16x2.f32 %0, %1, %2;" : "=r"(r) : "f"(hi), "f"(lo));
  return r;
}
__device__ __forceinline__ void ldsm4(uint32_t* r, uint32_t a){
  asm volatile("ldmatrix.sync.aligned.m8n8.x4.shared.b16 {%0,%1,%2,%3}, [%4];"
    : "=r"(r[0]),"=r"(r[1]),"=r"(r[2]),"=r"(r[3]) : "r"(a));
}
__device__ __forceinline__ void sts128(uint32_t a, uint4 v){
  asm volatile("st.shared.v4.b32 [%0], {%1,%2,%3,%4};"
    :: "r"(a), "r"(v.x), "r"(v.y), "r"(v.z), "r"(v.w));
}
__device__ __forceinline__ void mma16816(float* d, const uint32_t* a, const uint32_t* b){
  asm volatile(
    "mma.sync.aligned.m16n8k16.row.col.f32.f16.f16.f32 "
    "{%0,%1,%2,%3},{%4,%5,%6,%7},{%8,%9},{%0,%1,%2,%3};"
    : "+f"(d[0]),"+f"(d[1]),"+f"(d[2]),"+f"(d[3])
    : "r"(a[0]),"r"(a[1]),"r"(a[2]),"r"(a[3]), "r"(b[0]),"r"(b[1]));
}
__device__ __forceinline__ void red2(float* p, float x, float y){
  asm volatile("red.global.add.v2.f32 [%0], {%1,%2};" :: "l"(p), "f"(x), "f"(y) : "memory");
}
// row -> swizzled byte offset (64B pitch, 32 fp16 k-values per row)
__device__ __forceinline__ uint32_t swz(uint32_t r){
  return (r << 6) ^ (((r >> 1) & 3u) << 4);
}
// load 8 fp32 -> 16B fp16
__device__ __forceinline__ uint4 ld8cvt(const float* s){
  float4 u = *(const float4*)s; float4 v = *(const float4*)(s+4);
  uint4 r; r.x = f22h(u.x,u.y); r.y = f22h(u.z,u.w);
  r.z = f22h(v.x,v.y); r.w = f22h(v.z,v.w);
  return r;
}

// ---------------- small kernels ----------------
__global__ void zero_out_kernel(float* __restrict__ out){
  int i = blockIdx.x*256 + threadIdx.x;
  if (i < NTOK*HD) out[i] = 0.f;
}
__global__ void cvt_x_kernel(const float* __restrict__ X){
  int i = blockIdx.x*256 + threadIdx.x;   // i indexes pairs
  if (i < NTOK*HD/2){
    float2 v = ((const float2*)X)[i];
    ((uint32_t*)g_xh)[i] = f22h(v.x, v.y);
  }
}

__global__ void route_kernel(const int* __restrict__ idx, const float* __restrict__ w){
  __shared__ int cnt[NE];
  __shared__ int cur[NE];
  __shared__ int soff[NE+1];
  int tid = threadIdx.x;
  if (tid < NE) cnt[tid] = 0;
  __syncthreads();
  for (int i = tid; i < NP; i += blockDim.x) atomicAdd(&cnt[idx[i]], 1);
  __syncthreads();
  if (tid == 0){
    int s = 0, nm = 0;
    for (int e = 0; e < NE; e++){
      soff[e] = s;
      for (int j = 0; j < cnt[e]; j += BM){ g_mt_e[nm] = e; g_mt_r[nm] = s + j; nm++; }
      s += cnt[e];
    }
    soff[NE] = s;
    g_nmt = nm;
  }
  __syncthreads();
  if (tid <= NE) g_off[tid] = soff[tid];
  if (tid <  NE) cur[tid]  = soff[tid];
  __syncthreads();
  for (int i = tid; i < NP; i += blockDim.x){
    int e = idx[i];
    int p = atomicAdd(&cur[e], 1);
    g_perm[p] = i / TOPK;
    g_pw[p]   = w[i];
  }
}

// =================== GEMM1 ===================
// Block 256 tokens x 64 channels (gate+up). Smem rows (64B each):
// [0,256) A tokens fp16, [256,320) gate, [320,384) up. 24KB/stage, 48KB total.
// 8 warps = 4mw x 2nw; warp tile 64m x 32ch (gate+up dual accumulators).
#define G1_STAGE 24576
#define G1_SMEM  49152
#define G1_NKT   (HD/32)   // 64

__global__ __launch_bounds__(256,1) void gemm1_kernel(const float* __restrict__ GU)
{
  const int mt = blockIdx.x;
  if (mt >= g_nmt) return;
  const int e = g_mt_e[mt], row0 = g_mt_r[mt], pend = g_off[e+1];
  const int i0 = blockIdx.y * 64;

  extern __shared__ char smem[];
  const uint32_t sb = smem_u32(smem);
  const int t = threadIdx.x, lane = t & 31, wid = t >> 5;
  const int mw = wid & 3, nw = wid >> 2;       // 4m x 2n warps

  // ---- producer: 4 threads/row, 64 rows/pass; A 4 passes, gate 1, up 1 ----
  const int lr = t >> 2, q = t & 3;
  const __half* srcA[4];
  uint32_t oA[4];
  #pragma unroll
  for (int j = 0; j < 4; j++){
    int p = row0 + lr + 64*j;
    int pc = (p < pend) ? p : row0;
    srcA[j] = g_xh + (size_t)g_perm[pc]*HD + q*8;
    oA[j] = swz(lr + 64*j) ^ (q << 4);
  }
  const float* gu_e = GU + (size_t)e*(2*ID)*HD;
  const float* srcG = gu_e + (size_t)(i0 + lr)*HD + q*8;
  const float* srcU = gu_e + (size_t)(ID + i0 + lr)*HD + q*8;
  const uint32_t oG = swz(256 + lr) ^ (q << 4);
  const uint32_t oU = swz(320 + lr) ^ (q << 4);

  // ---- consumer fragment base offsets ----
  const uint32_t kh = (uint32_t)(lane >> 4) << 4;
  uint32_t pa[4];
  #pragma unroll
  for (int mi = 0; mi < 4; mi++)
    pa[mi] = swz(mw*64 + mi*16 + (lane & 15)) ^ kh;
  const int brl = (lane & 7) + (((lane >> 4) & 1) << 3);
  const uint32_t ch = (uint32_t)((lane >> 3) & 1) << 4;
  uint32_t pg[2], pu[2];
  #pragma unroll
  for (int j = 0; j < 2; j++){
    pg[j] = swz(256 + nw*32 + j*16 + brl) ^ ch;
    pu[j] = swz(320 + nw*32 + j*16 + brl) ^ ch;
  }

  float accg[4][4][4] = {}, accu[4][4][4] = {};

  // preload k-chunk 0
  #pragma unroll
  for (int j = 0; j < 4; j++) sts128(sb + oA[j], *(const uint4*)srcA[j]);
  sts128(sb + oG, ld8cvt(srcG));
  sts128(sb + oU, ld8cvt(srcU));
  __syncthreads();

  for (int kt = 0; kt < G1_NKT; kt++){
    const uint32_t sbuf = sb + (uint32_t)(kt & 1)*G1_STAGE;
    uint4 fA[4], fG, fU;
    if (kt + 1 < G1_NKT){
      const int ko = (kt + 1)*32;
      #pragma unroll
      for (int j = 0; j < 4; j++) fA[j] = *(const uint4*)(srcA[j] + ko);
      fG = ld8cvt(srcG + ko); fU = ld8cvt(srcU + ko);
    }
    #pragma unroll
    for (int ks = 0; ks < 2; ks++){
      const uint32_t k5 = (uint32_t)ks << 5;
      uint32_t A[16], Bg[8], Bu[8];
      #pragma unroll
      for (int mi = 0; mi < 4; mi++) ldsm4(A + mi*4, sbuf + (pa[mi] ^ k5));
      ldsm4(Bg,   sbuf + (pg[0] ^ k5));
      ldsm4(Bg+4, sbuf + (pg[1] ^ k5));
      ldsm4(Bu,   sbuf + (pu[0] ^ k5));
      ldsm4(Bu+4, sbuf + (pu[1] ^ k5));
      #pragma unroll
      for (int mi = 0; mi < 4; mi++){
        #pragma unroll
        for (int ni = 0; ni < 4; ni++){
          mma16816(accg[mi][ni], A + mi*4, Bg + ni*2);
          mma16816(accu[mi][ni], A + mi*4, Bu + ni*2);
        }
      }
    }
    if (kt + 1 < G1_NKT){
      const uint32_t dbuf = sb + (uint32_t)((kt + 1) & 1)*G1_STAGE;
      #pragma unroll
      for (int j = 0; j < 4; j++) sts128(dbuf + oA[j], fA[j]);
      sts128(dbuf + oG, fG); sts128(dbuf + oU, fU);
      __syncthreads();
    }
  }

  // ---- epilogue: silu(gate)*up*router_weight -> g_act fp16 ----
  const int g = lane >> 2, c = lane & 3;
  #pragma unroll
  for (int mi = 0; mi < 4; mi++){
    #pragma unroll
    for (int h = 0; h < 2; h++){
      int R = mw*64 + mi*16 + g + 8*h;
      int p = row0 + R;
      if (p < pend){
        float wgt = g_pw[p];
        __half* arow = g_act + (size_t)p*ID + i0 + nw*32 + 2*c;
        #pragma unroll
        for (int ni = 0; ni < 4; ni++){
          float gv0 = accg[mi][ni][2*h],   gv1 = accg[mi][ni][2*h+1];
          float uv0 = accu[mi][ni][2*h],   uv1 = accu[mi][ni][2*h+1];
          float o0 = wgt * (gv0 / (1.f + __expf(-gv0))) * uv0;
          float o1 = wgt * (gv1 / (1.f + __expf(-gv1))) * uv1;
          *(__half2*)(arow + ni*8) = __floats2half2_rn(o0, o1);
        }
      }
    }
  }
}

// =================== GEMM2 ===================
// Block 256 act-rows x 128 h-channels. Smem rows: [0,256) A fp16,
// [256,384) down. 24KB/stage, 48KB. 8 warps = 4mw x 2nw; warp 64m x 64n.
#define G2_STAGE 24576
#define G2_SMEM  49152
#define G2_NKT   (ID/32)   // 48

__global__ __launch_bounds__(256,1) void gemm2_kernel(const float* __restrict__ DW,
                                                      float* __restrict__ out)
{
  const int mt = blockIdx.x;
  if (mt >= g_nmt) return;
  const int e = g_mt_e[mt], row0 = g_mt_r[mt], pend = g_off[e+1];
  const int h0 = blockIdx.y * 128;

  extern __shared__ char smem[];
  const uint32_t sb = smem_u32(smem);
  const int t = threadIdx.x, lane = t & 31, wid = t >> 5;
  const int mw = wid & 3, nw = wid >> 2;

  // ---- producer: A 4 passes (256 rows), B 2 passes (128 rows) ----
  const int lr = t >> 2, q = t & 3;
  const __half* srcA[4];
  uint32_t oA[4];
  #pragma unroll
  for (int j = 0; j < 4; j++){
    int p = row0 + lr + 64*j;
    int pc = (p < pend) ? p : row0;
    srcA[j] = g_act + (size_t)pc*ID + q*8;
    oA[j] = swz(lr + 64*j) ^ (q << 4);
  }
  const float* dw_e = DW + (size_t)e*HD*ID;
  const float* srcB[2];
  uint32_t oB[2];
  #pragma unroll
  for (int j = 0; j < 2; j++){
    srcB[j] = dw_e + (size_t)(h0 + lr + 64*j)*ID + q*8;
    oB[j] = swz(256 + lr + 64*j) ^ (q << 4);
  }

  // ---- consumer fragment offsets ----
  const uint32_t kh = (uint32_t)(lane >> 4) << 4;
  uint32_t pa[4];
  #pragma unroll
  for (int mi = 0; mi < 4; mi++)
    pa[mi] = swz(mw*64 + mi*16 + (lane & 15)) ^ kh;
  const int brl = (lane & 7) + (((lane >> 4) & 1) << 3);
  const uint32_t chs = (uint32_t)((lane >> 3) & 1) << 4;
  uint32_t pb[4];
  #pragma unroll
  for (int j = 0; j < 4; j++)
    pb[j] = swz(256 + nw*64 + j*16 + brl) ^ chs;

  float acc[4][8][4] = {};

  // preload
  #pragma unroll
  for (int j = 0; j < 4; j++) sts128(sb + oA[j], *(const uint4*)srcA[j]);
  #pragma unroll
  for (int j = 0; j < 2; j++) sts128(sb + oB[j], ld8cvt(srcB[j]));
  __syncthreads();

  for (int kt = 0; kt < G2_NKT; kt++){
    const uint32_t sbuf = sb + (uint32_t)(kt & 1)*G2_STAGE;
    uint4 fA[4], fB[2];
    if (kt + 1 < G2_NKT){
      const int ko = (kt + 1)*32;
      #pragma unroll
      for (int j = 0; j < 4; j++) fA[j] = *(const uint4*)(srcA[j] + ko);
      #pragma unroll
      for (int j = 0; j < 2; j++) fB[j] = ld8cvt(srcB[j] + ko);
    }
    #pragma unroll
    for (int ks = 0; ks < 2; ks++){
      const uint32_t k5 = (uint32_t)ks << 5;
      uint32_t A[16], B[16];
      #pragma unroll
      for (int mi = 0; mi < 4; mi++) ldsm4(A + mi*4, sbuf + (pa[mi] ^ k5));
      #pragma unroll
      for (int j = 0; j < 4; j++)  ldsm4(B + j*4,  sbuf + (pb[j] ^ k5));
      #pragma unroll
      for (int mi = 0; mi < 4; mi++){
        #pragma unroll
        for (int ni = 0; ni < 8; ni++){
          mma16816(acc[mi][ni], A + mi*4, B + ni*2);
        }
      }
    }
    if (kt + 1 < G2_NKT){
      const uint32_t dbuf = sb + (uint32_t)((kt + 1) & 1)*G2_STAGE;
      #pragma unroll
      for (int j = 0; j < 4; j++) sts128(dbuf + oA[j], fA[j]);
      #pragma unroll
      for (int j = 0; j < 2; j++) sts128(dbuf + oB[j], fB[j]);
      __syncthreads();
    }
  }

  // ---- epilogue: vector scatter-add into out[token, h] ----
  const int g = lane >> 2, c = lane & 3;
  #pragma unroll
  for (int mi = 0; mi < 4; mi++){
    #pragma unroll
    for (int h = 0; h < 2; h++){
      int R = mw*64 + mi*16 + g + 8*h;
      int p = row0 + R;
      if (p < pend){
        int tok = g_perm[p];
        float* orow = out + (size_t)tok*HD + h0 + nw*64 + 2*c;
        #pragma unroll
        for (int ni = 0; ni < 8; ni++){
          red2(orow + ni*8, acc[mi][ni][2*h], acc[mi][ni][2*h+1]);
        }
      }
    }
  }
}

// ---------------- launch ----------------
extern "C" void kernel_launch(void* const* d_in, const int* in_sizes, int n_in,
                              void* d_out, int out_size)
{
  const float* X  = (const float*)d_in[0];
  const int*   ix = (const int*)d_in[1];
  const float* tw = (const float*)d_in[2];
  const float* GU = (const float*)d_in[3];
  const float* DW = (const float*)d_in[4];
  float* out = (float*)d_out;
  (void)in_sizes; (void)n_in; (void)out_size;

  cudaFuncSetAttribute(gemm1_kernel, cudaFuncAttributeMaxDynamicSharedMemorySize, G1_SMEM);
  cudaFuncSetAttribute(gemm2_kernel, cudaFuncAttributeMaxDynamicSharedMemorySize, G2_SMEM);

  zero_out_kernel<<<(NTOK*HD + 255)/256, 256>>>(out);
  cvt_x_kernel<<<(NTOK*HD/2 + 255)/256, 256>>>(X);
  route_kernel<<<1, 256>>>(ix, tw);
  gemm1_kernel<<<dim3(MAXMT, ID/64),  256, G1_SMEM>>>(GU);
  gemm2_kernel<<<dim3(MAXMT, HD/128), 256, G2_SMEM>>>(DW, out);
}

// round 8
// speedup vs baseline: 1.1923x; 1.1923x over previous
#include <cuda_runtime.h>
#include <cuda_fp16.h>
#include <cstdint>
#include <math.h>

// Problem sizes (fixed)
#define NE   32
#define HD   2048
#define ID   1536
#define NTOK 1024
#define TOPK 8
#define NP   (NTOK*TOPK)
#define BM   128
#define MAXMT 96

// ---------------- device scratch ----------------
__device__ int    g_perm[NP];
__device__ float  g_pw[NP];
__device__ int    g_off[NE+1];
__device__ int    g_mt_e[MAXMT];
__device__ int    g_mt_r[MAXMT];
__device__ int    g_nmt;
__device__ __half g_xh[(size_t)NTOK*HD];  // 4 MB fp16 hidden states
__device__ __half g_act[(size_t)NP*ID];   // 24 MB fp16 activations

// ---------------- helpers ----------------
__device__ __forceinline__ uint32_t smem_u32(const void* p){
  uint32_t a;
  asm("{ .reg .u64 t; cvta.to.shared.u64 t, %1; cvt.u32.u64 %0, t; }" : "=r"(a) : "l"(p));
  return a;
}
__device__ __forceinline__ uint32_t f22h(float lo, float hi){
  uint32_t r; asm("cvt.rn.f16x2.f32 %0, %1, %2;" : "=r"(r) : "f"(hi), "f"(lo));
  return r;
}
__device__ __forceinline__ void ldsm4(uint32_t* r, uint32_t a){
  asm volatile("ldmatrix.sync.aligned.m8n8.x4.shared.b16 {%0,%1,%2,%3}, [%4];"
    : "=r"(r[0]),"=r"(r[1]),"=r"(r[2]),"=r"(r[3]) : "r"(a));
}
__device__ __forceinline__ void sts128(uint32_t a, uint4 v){
  asm volatile("st.shared.v4.b32 [%0], {%1,%2,%3,%4};"
    :: "r"(a), "r"(v.x), "r"(v.y), "r"(v.z), "r"(v.w));
}
__device__ __forceinline__ void cpasync16(uint32_t dst, const void* src){
  asm volatile("cp.async.cg.shared.global [%0], [%1], 16;" :: "r"(dst), "l"(src));
}
#define CP_COMMIT() asm volatile("cp.async.commit_group;" ::: "memory")
#define CP_WAIT1()  asm volatile("cp.async.wait_group 1;" ::: "memory")
#define CP_WAIT0()  asm volatile("cp.async.wait_group 0;" ::: "memory")
__device__ __forceinline__ void mma16816(float* d, const uint32_t* a, const uint32_t* b){
  asm volatile(
    "mma.sync.aligned.m16n8k16.row.col.f32.f16.f16.f32 "
    "{%0,%1,%2,%3},{%4,%5,%6,%7},{%8,%9},{%0,%1,%2,%3};"
    : "+f"(d[0]),"+f"(d[1]),"+f"(d[2]),"+f"(d[3])
    : "r"(a[0]),"r"(a[1]),"r"(a[2]),"r"(a[3]), "r"(b[0]),"r"(b[1]));
}
__device__ __forceinline__ void red2(float* p, float x, float y){
  asm volatile("red.global.add.v2.f32 [%0], {%1,%2};" :: "l"(p), "f"(x), "f"(y) : "memory");
}
// row -> swizzled byte offset (64B pitch, 32 fp16 k-values per row)
__device__ __forceinline__ uint32_t swz(uint32_t r){
  return (r << 6) ^ (((r >> 1) & 3u) << 4);
}
// load 8 fp32 -> 16B fp16
__device__ __forceinline__ uint4 ld8cvt(const float* s){
  float4 u = *(const float4*)s; float4 v = *(const float4*)(s+4);
  uint4 r; r.x = f22h(u.x,u.y); r.y = f22h(u.z,u.w);
  r.z = f22h(v.x,v.y); r.w = f22h(v.z,v.w);
  return r;
}

// ---------------- small kernels ----------------
__global__ void zero_out_kernel(float* __restrict__ out){
  int i = blockIdx.x*256 + threadIdx.x;
  if (i < NTOK*HD) out[i] = 0.f;
}
__global__ void cvt_x_kernel(const float* __restrict__ X){
  int i = blockIdx.x*256 + threadIdx.x;
  if (i < NTOK*HD/2){
    float2 v = ((const float2*)X)[i];
    ((uint32_t*)g_xh)[i] = f22h(v.x, v.y);
  }
}

__global__ void route_kernel(const int* __restrict__ idx, const float* __restrict__ w){
  __shared__ int cnt[NE];
  __shared__ int cur[NE];
  __shared__ int soff[NE+1];
  int tid = threadIdx.x;
  if (tid < NE) cnt[tid] = 0;
  __syncthreads();
  for (int i = tid; i < NP; i += blockDim.x) atomicAdd(&cnt[idx[i]], 1);
  __syncthreads();
  if (tid == 0){
    int s = 0, nm = 0;
    for (int e = 0; e < NE; e++){
      soff[e] = s;
      for (int j = 0; j < cnt[e]; j += BM){ g_mt_e[nm] = e; g_mt_r[nm] = s + j; nm++; }
      s += cnt[e];
    }
    soff[NE] = s;
    g_nmt = nm;
  }
  __syncthreads();
  if (tid <= NE) g_off[tid] = soff[tid];
  if (tid <  NE) cur[tid]  = soff[tid];
  __syncthreads();
  for (int i = tid; i < NP; i += blockDim.x){
    int e = idx[i];
    int p = atomicAdd(&cur[e], 1);
    g_perm[p] = i / TOPK;
    g_pw[p]   = w[i];
  }
}

// =================== GEMM1 ===================
// Block 128 tokens x 128 channels (gate+up). Smem rows per stage:
// [0,128) A fp16, [128,256) gate, [256,384) up. 24KB/stage, 3 stages = 72KB.
#define G1_STAGE 24576
#define G1_SMEM  73728
#define G1_NKT   (HD/32)   // 64

__global__ __launch_bounds__(512,1) void gemm1_kernel(const float* __restrict__ GU)
{
  const int mt = blockIdx.x;
  if (mt >= g_nmt) return;
  const int e = g_mt_e[mt], row0 = g_mt_r[mt], pend = g_off[e+1];
  const int i0 = blockIdx.y * 128;

  extern __shared__ char smem[];
  const uint32_t sb = smem_u32(smem);
  const int t = threadIdx.x, lane = t & 31, wid = t >> 5;
  const int mw = wid & 3, nw = wid >> 2;       // 4m x 4n warps

  // ---- producer: 4 threads/row, 128 rows/pass; A, gate, up ----
  const int lr = t >> 2, q = t & 3;
  int pa = row0 + lr; int pc = (pa < pend) ? pa : row0;
  const __half* srcA = g_xh + (size_t)g_perm[pc]*HD + q*8;
  const float* gu_e = GU + (size_t)e*(2*ID)*HD;
  const float* srcG = gu_e + (size_t)(i0 + lr)*HD + q*8;
  const float* srcU = gu_e + (size_t)(ID + i0 + lr)*HD + q*8;
  const uint32_t sA = swz(lr) ^ (q << 4);
  const uint32_t sG = sA + 8192, sU = sA + 16384;

  // ---- consumer fragment base offsets ----
  const uint32_t ca = (uint32_t)(lane >> 4) << 4;
  const uint32_t pa0 = swz(mw*32 + (lane & 15)) ^ ca;
  const uint32_t pa1 = swz(mw*32 + 16 + (lane & 15)) ^ ca;
  const int brl = (lane & 7) + (((lane >> 4) & 1) << 3);
  const uint32_t cb = (uint32_t)((lane >> 3) & 1) << 4;
  const uint32_t pg0 = swz(128 + nw*32 + brl) ^ cb;
  const uint32_t pg1 = swz(128 + nw*32 + 16 + brl) ^ cb;
  const uint32_t pu0 = pg0 + 8192;
  const uint32_t pu1 = pg1 + 8192;

  float accg[2][4][4] = {}, accu[2][4][4] = {};

  const uint32_t b0 = sb, b1 = sb + G1_STAGE, b2 = sb + 2*G1_STAGE;

  // ---- prologue: fill stages 0,1; preload B regs for stage 2 ----
  cpasync16(b0 + sA, srcA);
  CP_COMMIT();
  sts128(b0 + sG, ld8cvt(srcG));
  sts128(b0 + sU, ld8cvt(srcU));
  cpasync16(b1 + sA, srcA + 32);
  CP_COMMIT();
  sts128(b1 + sG, ld8cvt(srcG + 32));
  sts128(b1 + sU, ld8cvt(srcU + 32));
  uint4 fG = ld8cvt(srcG + 64);
  uint4 fU = ld8cvt(srcU + 64);
  CP_WAIT1();
  __syncthreads();

  uint32_t cons = b0, nxt = b1, fill = b2;
  for (int kt = 0; kt < G1_NKT; kt++){
    const int k2 = kt + 2;
    if (k2 < G1_NKT){
      cpasync16(fill + sA, srcA + k2*32);
      sts128(fill + sG, fG);
      sts128(fill + sU, fU);
      CP_COMMIT();
      if (k2 + 1 < G1_NKT){
        fG = ld8cvt(srcG + (k2+1)*32);
        fU = ld8cvt(srcU + (k2+1)*32);
      }
    }
    #pragma unroll
    for (int ks = 0; ks < 2; ks++){
      const uint32_t k5 = (uint32_t)ks << 5;
      uint32_t A0[4], A1[4], Bg[8], Bu[8];
      ldsm4(A0,   cons + (pa0 ^ k5));
      ldsm4(A1,   cons + (pa1 ^ k5));
      ldsm4(Bg,   cons + (pg0 ^ k5));
      ldsm4(Bg+4, cons + (pg1 ^ k5));
      ldsm4(Bu,   cons + (pu0 ^ k5));
      ldsm4(Bu+4, cons + (pu1 ^ k5));
      #pragma unroll
      for (int ni = 0; ni < 4; ni++){
        mma16816(accg[0][ni], A0, Bg + ni*2);
        mma16816(accg[1][ni], A1, Bg + ni*2);
        mma16816(accu[0][ni], A0, Bu + ni*2);
        mma16816(accu[1][ni], A1, Bu + ni*2);
      }
    }
    if (kt + 1 < G1_NKT){
      if (k2 < G1_NKT) CP_WAIT1(); else CP_WAIT0();
      __syncthreads();
      uint32_t tmp = cons; cons = nxt; nxt = fill; fill = tmp;
    }
  }

  // ---- epilogue: silu(gate)*up*router_weight -> g_act fp16 ----
  const int g = lane >> 2, c = lane & 3;
  #pragma unroll
  for (int mi = 0; mi < 2; mi++){
    #pragma unroll
    for (int h = 0; h < 2; h++){
      int R = mw*32 + mi*16 + g + 8*h;
      int p = row0 + R;
      if (p < pend){
        float wgt = g_pw[p];
        __half* arow = g_act + (size_t)p*ID + i0 + nw*32 + 2*c;
        #pragma unroll
        for (int ni = 0; ni < 4; ni++){
          float gv0 = accg[mi][ni][2*h],   gv1 = accg[mi][ni][2*h+1];
          float uv0 = accu[mi][ni][2*h],   uv1 = accu[mi][ni][2*h+1];
          float o0 = wgt * (gv0 / (1.f + __expf(-gv0))) * uv0;
          float o1 = wgt * (gv1 / (1.f + __expf(-gv1))) * uv1;
          *(__half2*)(arow + ni*8) = __floats2half2_rn(o0, o1);
        }
      }
    }
  }
}

// =================== GEMM2 ===================
// Block 128 act-rows x 128 h-channels. Smem rows per stage: [0,128) A fp16,
// [128,256) down. 16KB/stage, 3 stages = 48KB. 256 thr, 2 CTAs/SM.
#define G2_STAGE 16384
#define G2_SMEM  49152
#define G2_NKT   (ID/32)   // 48

__global__ __launch_bounds__(256,2) void gemm2_kernel(const float* __restrict__ DW,
                                                      float* __restrict__ out)
{
  const int mt = blockIdx.x;
  if (mt >= g_nmt) return;
  const int e = g_mt_e[mt], row0 = g_mt_r[mt], pend = g_off[e+1];
  const int h0 = blockIdx.y * 128;

  extern __shared__ char smem[];
  const uint32_t sb = smem_u32(smem);
  const int t = threadIdx.x, lane = t & 31, wid = t >> 5;
  const int mw = wid & 3, nw = wid >> 2;       // 4m x 2n warps (32m x 64n each)

  // ---- producer: 4 threads/row; A 128 rows (2 passes), B 128 rows (2 passes)
  const int lr = t >> 2, q = t & 3;
  const __half* srcA[2];
  const float*  srcB[2];
  uint32_t sAo[2], sBo[2];
  const float* dw_e = DW + (size_t)e*HD*ID;
  #pragma unroll
  for (int j = 0; j < 2; j++){
    int r = lr + j*64;
    int p = row0 + r; int pcl = (p < pend) ? p : row0;
    srcA[j] = g_act + (size_t)pcl*ID + q*8;
    srcB[j] = dw_e + (size_t)(h0 + r)*ID + q*8;
    sAo[j] = swz(r) ^ (q << 4);
    sBo[j] = sAo[j] + 8192;
  }

  // ---- consumer fragment offsets ----
  const uint32_t ca = (uint32_t)(lane >> 4) << 4;
  const uint32_t pa0 = swz(mw*32 + (lane & 15)) ^ ca;
  const uint32_t pa1 = swz(mw*32 + 16 + (lane & 15)) ^ ca;
  const int brl = (lane & 7) + (((lane >> 4) & 1) << 3);
  const uint32_t cb = (uint32_t)((lane >> 3) & 1) << 4;
  uint32_t pb[4];
  #pragma unroll
  for (int j = 0; j < 4; j++)
    pb[j] = swz(128 + nw*64 + j*16 + brl) ^ cb;

  float acc[2][8][4] = {};

  const uint32_t b0 = sb, b1 = sb + G2_STAGE, b2 = sb + 2*G2_STAGE;

  // ---- prologue ----
  cpasync16(b0 + sAo[0], srcA[0]);
  cpasync16(b0 + sAo[1], srcA[1]);
  CP_COMMIT();
  sts128(b0 + sBo[0], ld8cvt(srcB[0]));
  sts128(b0 + sBo[1], ld8cvt(srcB[1]));
  cpasync16(b1 + sAo[0], srcA[0] + 32);
  cpasync16(b1 + sAo[1], srcA[1] + 32);
  CP_COMMIT();
  sts128(b1 + sBo[0], ld8cvt(srcB[0] + 32));
  sts128(b1 + sBo[1], ld8cvt(srcB[1] + 32));
  uint4 fB0 = ld8cvt(srcB[0] + 64);
  uint4 fB1 = ld8cvt(srcB[1] + 64);
  CP_WAIT1();
  __syncthreads();

  uint32_t cons = b0, nxt = b1, fill = b2;
  for (int kt = 0; kt < G2_NKT; kt++){
    const int k2 = kt + 2;
    if (k2 < G2_NKT){
      cpasync16(fill + sAo[0], srcA[0] + k2*32);
      cpasync16(fill + sAo[1], srcA[1] + k2*32);
      sts128(fill + sBo[0], fB0);
      sts128(fill + sBo[1], fB1);
      CP_COMMIT();
      if (k2 + 1 < G2_NKT){
        fB0 = ld8cvt(srcB[0] + (k2+1)*32);
        fB1 = ld8cvt(srcB[1] + (k2+1)*32);
      }
    }
    #pragma unroll
    for (int ks = 0; ks < 2; ks++){
      const uint32_t k5 = (uint32_t)ks << 5;
      uint32_t A0[4], A1[4], B[16];
      ldsm4(A0, cons + (pa0 ^ k5));
      ldsm4(A1, cons + (pa1 ^ k5));
      #pragma unroll
      for (int j = 0; j < 4; j++) ldsm4(B + j*4, cons + (pb[j] ^ k5));
      #pragma unroll
      for (int ni = 0; ni < 8; ni++){
        mma16816(acc[0][ni], A0, B + ni*2);
        mma16816(acc[1][ni], A1, B + ni*2);
      }
    }
    if (kt + 1 < G2_NKT){
      if (k2 < G2_NKT) CP_WAIT1(); else CP_WAIT0();
      __syncthreads();
      uint32_t tmp = cons; cons = nxt; nxt = fill; fill = tmp;
    }
  }

  // ---- epilogue: vector scatter-add into out[token, h] ----
  const int g = lane >> 2, c = lane & 3;
  #pragma unroll
  for (int mi = 0; mi < 2; mi++){
    #pragma unroll
    for (int h = 0; h < 2; h++){
      int R = mw*32 + mi*16 + g + 8*h;
      int p = row0 + R;
      if (p < pend){
        int tok = g_perm[p];
        float* orow = out + (size_t)tok*HD + h0 + nw*64 + 2*c;
        #pragma unroll
        for (int ni = 0; ni < 8; ni++){
          red2(orow + ni*8, acc[mi][ni][2*h], acc[mi][ni][2*h+1]);
        }
      }
    }
  }
}

// ---------------- launch ----------------
extern "C" void kernel_launch(void* const* d_in, const int* in_sizes, int n_in,
                              void* d_out, int out_size)
{
  const float* X  = (const float*)d_in[0];
  const int*   ix = (const int*)d_in[1];
  const float* tw = (const float*)d_in[2];
  const float* GU = (const float*)d_in[3];
  const float* DW = (const float*)d_in[4];
  float* out = (float*)d_out;
  (void)in_sizes; (void)n_in; (void)out_size;

  cudaFuncSetAttribute(gemm1_kernel, cudaFuncAttributeMaxDynamicSharedMemorySize, G1_SMEM);
  cudaFuncSetAttribute(gemm2_kernel, cudaFuncAttributeMaxDynamicSharedMemorySize, G2_SMEM);

  zero_out_kernel<<<(NTOK*HD + 255)/256, 256>>>(out);
  cvt_x_kernel<<<(NTOK*HD/2 + 255)/256, 256>>>(X);
  route_kernel<<<1, 256>>>(ix, tw);
  gemm1_kernel<<<dim3(MAXMT, ID/128), 512, G1_SMEM>>>(GU);
  gemm2_kernel<<<dim3(MAXMT, HD/128), 256, G2_SMEM>>>(DW, out);
}